// round 7
// baseline (speedup 1.0000x reference)
#include <cuda_runtime.h>
#include <cstdint>

// SpikeFP32ScaleBy2K — rows of 32 {0,1} floats = big-endian FP32 bit pattern.
// out = x with exponent += K (mod 256), K = 8-bit two's-complement
// (0x80|m_k[0..6]) >> (7 - ((e_k-127)&7)), negated if s_k; passthrough when
// k's exp+mantissa bits are all zero. Only elements 1..8 change.
//
// R7: same compute as R6 (element-order combined word, one 3-step shfl_xor
// OR-butterfly per 4-row group, scalar circuit on broadcast word, 16-entry
// SMEM LUT for output), but GROUPS=4 -> 8 LDG.128 in flight per thread to
// raise in-flight HBM bytes (the binding constraint). Streaming stores
// (__stcs) keep L2 clean for the two read streams; loads stay default.
//
// Combined word C (element-order, bit = element value):
//   [0:12)   x elements 0..11   (lanes c=0..2; only bits 1..8 consumed)
//   [12:28)  k elements 0..15   (lanes c=0..3)
//   [28]     OR of k elements 16..31 (lanes c=4..7)

static constexpr int GROUPS = 4;                 // 4 rows/group, 16 rows/warp
static constexpr unsigned ONEF = 0x3F800000u;

__device__ __forceinline__ unsigned pack_nib(uint4 u) {
    // components are exactly 0x00000000 or 0x3F800000
    unsigned a = min(u.x, 1u), b = min(u.y, 1u);
    unsigned c = min(u.z, 1u), d = min(u.w, 1u);
    return a | (b << 1) | (c << 2) | (d << 3);
}

__global__ void __launch_bounds__(256)
spike_scale_kernel(const uint4* __restrict__ x4,
                   const uint4* __restrict__ k4,
                   uint4* __restrict__ out4,
                   unsigned nrows) {
    __shared__ uint4 lut[16];
    if (threadIdx.x < 16) {
        unsigned n = threadIdx.x;
        lut[n] = make_uint4((n & 1u) * ONEF, ((n >> 1) & 1u) * ONEF,
                            ((n >> 2) & 1u) * ONEF, ((n >> 3) & 1u) * ONEF);
    }
    __syncthreads();

    const unsigned lane = threadIdx.x & 31u;
    const unsigned c    = lane & 7u;             // float4 chunk within row
    const unsigned sub  = lane >> 3;             // row within 4-row group
    const unsigned s4   = c * 4u;                // first element idx of chunk

    // per-lane constants
    const unsigned Ax   = (c <= 2u) ? (0xFu << s4) : 0u;        // x field
    const unsigned Ak   = (c <= 3u) ? (0xFu << (s4 + 12u)) : 0u;// k field
    const unsigned s4k  = (s4 + 12u) & 31u;
    const unsigned m0   = (c >= 4u) ? ~0u : 0u;  // k hi-half OR contributor
    const unsigned remm = (c == 0u) ? 0xEu : (c == 1u) ? 0xFu
                        : (c == 2u) ? 0x1u : 0u; // exponent components
    const unsigned sh_e = (23u + s4) & 31u;      // enew-bit slice position

    const unsigned warp_id = blockIdx.x * (blockDim.x >> 5) + (threadIdx.x >> 5);
    const unsigned row0 = warp_id * (4u * GROUPS);
    if (row0 >= nrows) return;                   // warp-uniform (after sync)

    const bool full = (row0 + 4u * GROUPS) <= nrows;

    // Front-batch ALL loads (8x LDG.128 per thread in flight), compress each
    // group to 3 small regs (nibX, nibK|knz flag, C-partial) as data lands.
    unsigned idx[GROUPS], safem[GROUPS];
    unsigned nibX[GROUPS], Cw[GROUPS];

    uint4 xv[GROUPS], kv[GROUPS];
    #pragma unroll
    for (int g = 0; g < GROUPS; g++) {
        unsigned row = row0 + 4u * g + sub;
        unsigned ok  = full | (row < nrows);
        safem[g] = 0u - (unsigned)ok;
        unsigned r = ok ? row : (nrows - 1u);    // clamp keeps loads in-bounds
        idx[g] = r * 8u + c;                     // max 2^24, fits 32-bit
        xv[g] = x4[idx[g]];
        kv[g] = k4[idx[g]];
    }

    #pragma unroll
    for (int g = 0; g < GROUPS; g++) {
        nibX[g] = pack_nib(xv[g]);
        unsigned nibK = pack_nib(kv[g]);
        unsigned kOr  = (kv[g].x | kv[g].y | kv[g].z | kv[g].w) & m0;
        Cw[g] = ((nibX[g] << s4) & Ax)
              | ((nibK << s4k) & Ak)
              | (min(kOr, 1u) << 28);
    }

    #pragma unroll
    for (int g = 0; g < GROUPS; g++) {
        unsigned C = Cw[g];
        C |= __shfl_xor_sync(~0u, C, 1);         // OR-butterfly (8-lane group)
        C |= __shfl_xor_sync(~0u, C, 2);
        C |= __shfl_xor_sync(~0u, C, 4);

        // ── scalar circuit (all reversals on the broadcast word) ──
        unsigned B    = __brev(C);
        unsigned ex   = (B >> 23) & 0xFFu;       // x elements 1..8, LSB=elem8
        unsigned ek   = (B >> 11) & 0xFFu;       // k elements 1..8
        unsigned val  = 0x80u | ((B >> 4) & 0x7Fu);   // 1.m_k[0..6]
        unsigned rs   = (6u - ek) & 7u;          // = 7 - ((ek-127)&7)
        unsigned kabs = val >> rs;
        unsigned neg  = 0u - ((C >> 12) & 1u);   // s_k
        unsigned kf   = (kabs ^ neg) - neg;
        unsigned enew = ex + kf;                 // low 8 bits valid
        unsigned knz4 = (C & 0x1FFFE000u) ? 0xFu : 0u;  // k exp|mant nonzero

        // per-lane output nibble: enew bits for exponent comps, else own nibX
        unsigned sel    = remm & knz4;
        unsigned en_nib = __brev(enew) >> sh_e;  // bit t = enew bit (8-s4-t)
        unsigned no     = (en_nib & sel) | (nibX[g] & ~sel);

        uint4 o = lut[no & 0xFu];
        if (safem[g]) __stcs(&out4[idx[g]], o);
    }
}

extern "C" void kernel_launch(void* const* d_in, const int* in_sizes, int n_in,
                              void* d_out, int out_size) {
    const uint4* x4 = (const uint4*)d_in[0];
    const uint4* k4 = (const uint4*)d_in[1];
    uint4* out4 = (uint4*)d_out;

    unsigned nrows = (unsigned)(in_sizes[0] / 32);

    const int threads = 256;                     // 8 warps
    const int rows_per_block = 8 * 4 * GROUPS;   // 128
    int blocks = (int)((nrows + rows_per_block - 1) / rows_per_block);

    spike_scale_kernel<<<blocks, threads>>>(x4, k4, out4, nrows);
}

// round 8
// speedup vs baseline: 1.0057x; 1.0057x over previous
#include <cuda_runtime.h>
#include <cstdint>

// SpikeFP32ScaleBy2K — rows of 32 {0,1} floats = big-endian FP32 bit pattern.
// out = x with exponent += K (mod 256), K = 8-bit two's-complement
// (0x80|m_k[0..6]) >> (7 - ((e_k-127)&7)), negated if s_k; passthrough when
// k's exp+mantissa bits are all zero. Only elements 1..8 change.
//
// R8 = best-of-R4-and-R6:
//   - R4 structure: GROUPS=2 (4 LDG.128/thread — below the cross-CTA L1tex
//     spread knee), NO shared memory / no __syncthreads, output rebuilt in
//     ALU (no LDS in the store path).
//   - R6 compute: element-order combined word, ONE 3-step shfl_xor
//     OR-butterfly per 4-row group, single __brev on the broadcast word,
//     per-lane nibble select for the output.
//   - 32-bit indexing, streaming stores (__stcs); loads default-cached.
//
// Combined word C (element-order, bit = element value):
//   [0:12)   x elements 0..11   (lanes c=0..2; only bits 1..8 consumed)
//   [12:28)  k elements 0..15   (lanes c=0..3)
//   [28]     OR of k elements 16..31 (lanes c=4..7)

static constexpr int GROUPS = 2;                 // 4 rows/group, 8 rows/warp
static constexpr unsigned ONEF = 0x3F800000u;

__device__ __forceinline__ unsigned pack_nib(uint4 u) {
    // components are exactly 0x00000000 or 0x3F800000
    unsigned a = min(u.x, 1u), b = min(u.y, 1u);
    unsigned c = min(u.z, 1u), d = min(u.w, 1u);
    return a | (b << 1) | (c << 2) | (d << 3);
}

__global__ void __launch_bounds__(256)
spike_scale_kernel(const uint4* __restrict__ x4,
                   const uint4* __restrict__ k4,
                   uint4* __restrict__ out4,
                   unsigned nrows) {
    const unsigned lane = threadIdx.x & 31u;
    const unsigned c    = lane & 7u;             // float4 chunk within row
    const unsigned sub  = lane >> 3;             // row within 4-row group
    const unsigned s4   = c * 4u;                // first element idx of chunk

    // per-lane constants
    const unsigned Ax   = (c <= 2u) ? (0xFu << s4) : 0u;        // x field
    const unsigned Ak   = (c <= 3u) ? (0xFu << (s4 + 12u)) : 0u;// k field
    const unsigned s4k  = (s4 + 12u) & 31u;
    const unsigned m0   = (c >= 4u) ? ~0u : 0u;  // k hi-half OR contributor
    const unsigned remm = (c == 0u) ? 0xEu : (c == 1u) ? 0xFu
                        : (c == 2u) ? 0x1u : 0u; // exponent components
    const unsigned sh_e = (23u + s4) & 31u;      // enew-bit slice position

    const unsigned warp_id = blockIdx.x * (blockDim.x >> 5) + (threadIdx.x >> 5);
    const unsigned row0 = warp_id * (4u * GROUPS);
    if (row0 >= nrows) return;                   // warp-uniform

    uint4 xv[GROUPS], kv[GROUPS];
    unsigned idx[GROUPS], safem[GROUPS];
    const bool full = (row0 + 4u * GROUPS) <= nrows;

    #pragma unroll
    for (int g = 0; g < GROUPS; g++) {
        unsigned row = row0 + 4u * g + sub;
        unsigned ok  = full | (row < nrows);
        safem[g] = 0u - (unsigned)ok;
        unsigned r = ok ? row : (nrows - 1u);    // clamp keeps loads in-bounds
        idx[g] = r * 8u + c;                     // max 2^24, fits 32-bit
        xv[g] = x4[idx[g]];
        kv[g] = k4[idx[g]];
    }

    #pragma unroll
    for (int g = 0; g < GROUPS; g++) {
        unsigned nibX = pack_nib(xv[g]);
        unsigned nibK = pack_nib(kv[g]);
        unsigned kOr  = (kv[g].x | kv[g].y | kv[g].z | kv[g].w) & m0;

        unsigned C = ((nibX << s4) & Ax)
                   | ((nibK << s4k) & Ak)
                   | (min(kOr, 1u) << 28);

        C |= __shfl_xor_sync(~0u, C, 1);         // OR-butterfly (8-lane group)
        C |= __shfl_xor_sync(~0u, C, 2);
        C |= __shfl_xor_sync(~0u, C, 4);

        // ── scalar circuit (reversals once, on the broadcast word) ──
        unsigned B    = __brev(C);
        unsigned ex   = (B >> 23) & 0xFFu;       // x elements 1..8, LSB=elem8
        unsigned ek   = (B >> 11) & 0xFFu;       // k elements 1..8
        unsigned val  = 0x80u | ((B >> 4) & 0x7Fu);   // 1.m_k[0..6]
        unsigned rs   = (6u - ek) & 7u;          // = 7 - ((ek-127)&7)
        unsigned kabs = val >> rs;
        unsigned neg  = 0u - ((C >> 12) & 1u);   // s_k
        unsigned kf   = (kabs ^ neg) - neg;
        unsigned enew = ex + kf;                 // low 8 bits valid
        unsigned knz4 = (C & 0x1FFFE000u) ? 0xFu : 0u;  // k exp|mant nonzero

        // per-lane output nibble: enew bits for exponent comps, else own nibX
        unsigned sel    = remm & knz4;
        unsigned en_nib = __brev(enew) >> sh_e;  // bit t = enew bit (8-s4-t)
        unsigned no     = (en_nib & sel) | (nibX & ~sel);

        uint4 o;
        o.x = (no        & 1u) * ONEF;           // raw 1.0f / 0.0f patterns
        o.y = ((no >> 1) & 1u) * ONEF;
        o.z = ((no >> 2) & 1u) * ONEF;
        o.w = ((no >> 3) & 1u) * ONEF;
        if (safem[g]) __stcs(&out4[idx[g]], o);
    }
}

extern "C" void kernel_launch(void* const* d_in, const int* in_sizes, int n_in,
                              void* d_out, int out_size) {
    const uint4* x4 = (const uint4*)d_in[0];
    const uint4* k4 = (const uint4*)d_in[1];
    uint4* out4 = (uint4*)d_out;

    unsigned nrows = (unsigned)(in_sizes[0] / 32);

    const int threads = 256;                     // 8 warps
    const int rows_per_block = 8 * 4 * GROUPS;   // 64
    int blocks = (int)((nrows + rows_per_block - 1) / rows_per_block);

    spike_scale_kernel<<<blocks, threads>>>(x4, k4, out4, nrows);
}

// round 9
// speedup vs baseline: 1.0151x; 1.0093x over previous
#include <cuda_runtime.h>
#include <cstdint>

// SpikeFP32ScaleBy2K — rows of 32 {0,1} floats = big-endian FP32 bit pattern.
// out = x with exponent += K (mod 256), K = 8-bit two's-complement
// (0x80|m_k[0..6]) >> (7 - ((e_k-127)&7)), negated if s_k; passthrough when
// k's exp+mantissa bits are all zero. Only elements 1..8 change.
//
// R9 = R8 with DEFAULT-cached stores (single-variable test).
// Evidence: R4 (default stores) hit 86.1% DRAM / 111.0us ncu — best of all
// rounds; every .cs-store round (R5-R8) sat at 83.7-85.2%. ALU level has
// proven non-binding (44-61% swings, flat dur), so the compute core stays
// the cheap R8 one:
//   - GROUPS=2: 4 front-batched LDG.128/thread (below L1tex spread knee)
//   - no shared memory, no __syncthreads
//   - element-order combined word, ONE 3-step shfl_xor OR-butterfly/group
//   - single __brev on the broadcast word, per-lane nibble output select
//   - 32-bit indexing
//
// Combined word C (element-order, bit = element value):
//   [0:12)   x elements 0..11   (lanes c=0..2; only bits 1..8 consumed)
//   [12:28)  k elements 0..15   (lanes c=0..3)
//   [28]     OR of k elements 16..31 (lanes c=4..7)

static constexpr int GROUPS = 2;                 // 4 rows/group, 8 rows/warp
static constexpr unsigned ONEF = 0x3F800000u;

__device__ __forceinline__ unsigned pack_nib(uint4 u) {
    // components are exactly 0x00000000 or 0x3F800000
    unsigned a = min(u.x, 1u), b = min(u.y, 1u);
    unsigned c = min(u.z, 1u), d = min(u.w, 1u);
    return a | (b << 1) | (c << 2) | (d << 3);
}

__global__ void __launch_bounds__(256)
spike_scale_kernel(const uint4* __restrict__ x4,
                   const uint4* __restrict__ k4,
                   uint4* __restrict__ out4,
                   unsigned nrows) {
    const unsigned lane = threadIdx.x & 31u;
    const unsigned c    = lane & 7u;             // float4 chunk within row
    const unsigned sub  = lane >> 3;             // row within 4-row group
    const unsigned s4   = c * 4u;                // first element idx of chunk

    // per-lane constants
    const unsigned Ax   = (c <= 2u) ? (0xFu << s4) : 0u;        // x field
    const unsigned Ak   = (c <= 3u) ? (0xFu << (s4 + 12u)) : 0u;// k field
    const unsigned s4k  = (s4 + 12u) & 31u;
    const unsigned m0   = (c >= 4u) ? ~0u : 0u;  // k hi-half OR contributor
    const unsigned remm = (c == 0u) ? 0xEu : (c == 1u) ? 0xFu
                        : (c == 2u) ? 0x1u : 0u; // exponent components
    const unsigned sh_e = (23u + s4) & 31u;      // enew-bit slice position

    const unsigned warp_id = blockIdx.x * (blockDim.x >> 5) + (threadIdx.x >> 5);
    const unsigned row0 = warp_id * (4u * GROUPS);
    if (row0 >= nrows) return;                   // warp-uniform

    uint4 xv[GROUPS], kv[GROUPS];
    unsigned idx[GROUPS], safem[GROUPS];
    const bool full = (row0 + 4u * GROUPS) <= nrows;

    #pragma unroll
    for (int g = 0; g < GROUPS; g++) {
        unsigned row = row0 + 4u * g + sub;
        unsigned ok  = full | (row < nrows);
        safem[g] = 0u - (unsigned)ok;
        unsigned r = ok ? row : (nrows - 1u);    // clamp keeps loads in-bounds
        idx[g] = r * 8u + c;                     // max 2^24, fits 32-bit
        xv[g] = x4[idx[g]];
        kv[g] = k4[idx[g]];
    }

    #pragma unroll
    for (int g = 0; g < GROUPS; g++) {
        unsigned nibX = pack_nib(xv[g]);
        unsigned nibK = pack_nib(kv[g]);
        unsigned kOr  = (kv[g].x | kv[g].y | kv[g].z | kv[g].w) & m0;

        unsigned C = ((nibX << s4) & Ax)
                   | ((nibK << s4k) & Ak)
                   | (min(kOr, 1u) << 28);

        C |= __shfl_xor_sync(~0u, C, 1);         // OR-butterfly (8-lane group)
        C |= __shfl_xor_sync(~0u, C, 2);
        C |= __shfl_xor_sync(~0u, C, 4);

        // ── scalar circuit (reversals once, on the broadcast word) ──
        unsigned B    = __brev(C);
        unsigned ex   = (B >> 23) & 0xFFu;       // x elements 1..8, LSB=elem8
        unsigned ek   = (B >> 11) & 0xFFu;       // k elements 1..8
        unsigned val  = 0x80u | ((B >> 4) & 0x7Fu);   // 1.m_k[0..6]
        unsigned rs   = (6u - ek) & 7u;          // = 7 - ((ek-127)&7)
        unsigned kabs = val >> rs;
        unsigned neg  = 0u - ((C >> 12) & 1u);   // s_k
        unsigned kf   = (kabs ^ neg) - neg;
        unsigned enew = ex + kf;                 // low 8 bits valid
        unsigned knz4 = (C & 0x1FFFE000u) ? 0xFu : 0u;  // k exp|mant nonzero

        // per-lane output nibble: enew bits for exponent comps, else own nibX
        unsigned sel    = remm & knz4;
        unsigned en_nib = __brev(enew) >> sh_e;  // bit t = enew bit (8-s4-t)
        unsigned no     = (en_nib & sel) | (nibX & ~sel);

        uint4 o;
        o.x = (0u - (no        & 1u)) & ONEF;    // raw 1.0f / 0.0f patterns
        o.y = (0u - ((no >> 1) & 1u)) & ONEF;
        o.z = (0u - ((no >> 2) & 1u)) & ONEF;
        o.w = (0u - ((no >> 3) & 1u)) & ONEF;
        if (safem[g]) out4[idx[g]] = o;          // DEFAULT-cached store
    }
}

extern "C" void kernel_launch(void* const* d_in, const int* in_sizes, int n_in,
                              void* d_out, int out_size) {
    const uint4* x4 = (const uint4*)d_in[0];
    const uint4* k4 = (const uint4*)d_in[1];
    uint4* out4 = (uint4*)d_out;

    unsigned nrows = (unsigned)(in_sizes[0] / 32);

    const int threads = 256;                     // 8 warps
    const int rows_per_block = 8 * 4 * GROUPS;   // 64
    int blocks = (int)((nrows + rows_per_block - 1) / rows_per_block);

    spike_scale_kernel<<<blocks, threads>>>(x4, k4, out4, nrows);
}